// round 5
// baseline (speedup 1.0000x reference)
#include <cuda_runtime.h>
#include <cuda_bf16.h>
#include <cstdint>

// Problem dims
#define MDIM 256
#define TDIM 512
#define NXDIM 256
#define UDIM 256

// Scratch for x-projections: 3 matrices x [T][M][U] fp32 = 402 MB.
// Layout per matrix: xp[((t*256 + m)*256) + u]  (linear in GEMM row g = t*256+m)
#define XP_STRIDE (33554432ULL) // 512*256*256
__device__ float g_xp[3ULL * XP_STRIDE];

// ---------------- packed f32x2 helpers ----------------
#define FFMA2(c_, a_, b_) \
    asm volatile("fma.rn.f32x2 %0, %1, %2, %0;" : "+l"(c_) : "l"(a_), "l"(b_))

__device__ __forceinline__ unsigned long long dup2(float a) {
    unsigned long long r;
    asm("mov.b64 %0, {%1, %1};" : "=l"(r) : "f"(a));
    return r;
}
__device__ __forceinline__ void unpack2(float& lo, float& hi, unsigned long long v) {
    asm("mov.b64 {%0, %1}, %2;" : "=f"(lo), "=f"(hi) : "l"(v));
}

// =====================================================================
// Phase 1: x projections.  C[g, n] = sum_k x_row(g)[k] * W[k][n]
//   g = t*256 + m  (so output is linear: xp + g*256 + n)
//   x row base = x + (m*T + t)*NX
// Tiles: BM=128, BN=128, BK=16.  grid = (1024, 2, 3), block = 256.
//   blockIdx.z: 0 -> wux (xu), 1 -> wrx (xr), 2 -> wcx (xc)
// =====================================================================
__global__ __launch_bounds__(256, 1)
void xproj_kernel(const float* __restrict__ x,
                  const float* __restrict__ w_u,
                  const float* __restrict__ w_r,
                  const float* __restrict__ w_c)
{
    const float* __restrict__ w =
        (blockIdx.z == 0) ? w_u : ((blockIdx.z == 1) ? w_r : w_c);
    float* __restrict__ outp = g_xp + (size_t)blockIdx.z * XP_STRIDE;

    const int tid = threadIdx.x;
    const int g0  = blockIdx.x * 128;
    const int t   = g0 >> 8;        // fixed for the whole tile (128 | 256)
    const int m0  = g0 & 255;       // 0 or 128
    const int n0  = blockIdx.y * 128;

    __shared__ float As[16][132];   // [k][m], padded
    __shared__ float Bs[16][128];   // [k][n]

    const int tx = tid & 15;        // 0..15 -> 8 cols each
    const int ty = tid >> 4;        // 0..15 -> 8 rows each

    unsigned long long acc[8][4];
    #pragma unroll
    for (int i = 0; i < 8; i++)
        #pragma unroll
        for (int j = 0; j < 4; j++) acc[i][j] = 0ULL;

    for (int kk = 0; kk < NXDIM; kk += 16) {
        // ---- load A tile (128 rows x 16 k), transposed into As[k][m] ----
        #pragma unroll
        for (int l = 0; l < 2; l++) {
            int f  = tid + l * 256;
            int i  = f >> 2;                 // row 0..127
            int kv = (f & 3) * 4;            // k sub-chunk
            const float4 v = *(const float4*)(x +
                ((size_t)(m0 + i) * TDIM + t) * NXDIM + kk + kv);
            As[kv + 0][i] = v.x;
            As[kv + 1][i] = v.y;
            As[kv + 2][i] = v.z;
            As[kv + 3][i] = v.w;
        }
        // ---- load B tile (16 k x 128 n) ----
        #pragma unroll
        for (int l = 0; l < 2; l++) {
            int f  = tid + l * 256;
            int k  = f >> 5;                 // 0..15
            int nn = (f & 31) * 4;
            *(float4*)&Bs[k][nn] =
                *(const float4*)(w + (size_t)(kk + k) * UDIM + n0 + nn);
        }
        __syncthreads();

        #pragma unroll
        for (int k = 0; k < 16; k++) {
            float4 a0v = *(const float4*)&As[k][ty * 8];
            float4 a1v = *(const float4*)&As[k][ty * 8 + 4];
            const unsigned long long* bp =
                (const unsigned long long*)&Bs[k][tx * 8];
            unsigned long long b0 = bp[0], b1 = bp[1], b2 = bp[2], b3 = bp[3];
            float av[8] = {a0v.x, a0v.y, a0v.z, a0v.w,
                           a1v.x, a1v.y, a1v.z, a1v.w};
            #pragma unroll
            for (int i = 0; i < 8; i++) {
                unsigned long long ad = dup2(av[i]);
                FFMA2(acc[i][0], ad, b0);
                FFMA2(acc[i][1], ad, b1);
                FFMA2(acc[i][2], ad, b2);
                FFMA2(acc[i][3], ad, b3);
            }
        }
        __syncthreads();
    }

    // ---- epilogue: write C (biases are added in phase 2) ----
    #pragma unroll
    for (int i = 0; i < 8; i++) {
        int g = g0 + ty * 8 + i;
        float o[8];
        unpack2(o[0], o[1], acc[i][0]);
        unpack2(o[2], o[3], acc[i][1]);
        unpack2(o[4], o[5], acc[i][2]);
        unpack2(o[6], o[7], acc[i][3]);
        float* op = outp + (size_t)g * UDIM + n0 + tx * 8;
        *(float4*)(op)     = make_float4(o[0], o[1], o[2], o[3]);
        *(float4*)(op + 4) = make_float4(o[4], o[5], o[6], o[7]);
    }
}

// =====================================================================
// Phase 2: sequential GRU scan.
// 64 CTAs x 4 batch rows; 256 threads, thread n owns output unit n for
// its 4 rows.  State c kept in registers (c_reg[4]) + broadcast smem
// copy c_s laid out [k][row] so row pairs are natural f32x2 operands.
// Weights streamed from L2 (resident: 768 KB << 126 MB, shared by all CTAs).
// =====================================================================
__device__ __forceinline__ float sigmoid_f(float z) {
    return 1.0f / (1.0f + __expf(-z));
}

__global__ __launch_bounds__(256, 1)
void gru_scan_kernel(const float* __restrict__ wuc,
                     const float* __restrict__ wrc,
                     const float* __restrict__ wcc,
                     const float* __restrict__ bu,
                     const float* __restrict__ br,
                     const float* __restrict__ bc,
                     const float* __restrict__ a0,
                     float* __restrict__ out)
{
    __shared__ float c_s[UDIM * 4];   // [k][r]
    __shared__ float h_s[UDIM * 4];   // [k][r]

    const int n  = threadIdx.x;       // output unit
    const int r0 = blockIdx.x * 4;    // first batch row

    const float* __restrict__ xu = g_xp;
    const float* __restrict__ xr = g_xp + XP_STRIDE;
    const float* __restrict__ xc = g_xp + 2ULL * XP_STRIDE;

    const float bun = bu[n];
    const float brn = br[n];
    const float bcn = bc[n];

    float c_reg[4];
    #pragma unroll
    for (int r = 0; r < 4; r++)
        c_reg[r] = a0[(size_t)(r0 + r) * UDIM + n];
    *(float4*)&c_s[n * 4] = make_float4(c_reg[0], c_reg[1], c_reg[2], c_reg[3]);
    __syncthreads();

    for (int t = 0; t < TDIM; t++) {
        // prefetch x projections for this step (hidden under phase-A GEMV)
        const size_t xb = ((size_t)t * MDIM + r0) * UDIM + n;
        float xu_[4], xr_[4], xc_[4];
        #pragma unroll
        for (int r = 0; r < 4; r++) {
            xu_[r] = __ldg(xu + xb + (size_t)r * UDIM);
            xr_[r] = __ldg(xr + xb + (size_t)r * UDIM);
            xc_[r] = __ldg(xc + xb + (size_t)r * UDIM);
        }

        // ---- phase A: pre_u = c @ wuc[:,n], pre_r = c @ wrc[:,n] ----
        unsigned long long au01 = 0ULL, au23 = 0ULL, ar01 = 0ULL, ar23 = 0ULL;
        #pragma unroll 16
        for (int k = 0; k < UDIM; k++) {
            unsigned long long a01 = *(const unsigned long long*)&c_s[k * 4];
            unsigned long long a23 = *(const unsigned long long*)&c_s[k * 4 + 2];
            unsigned long long wu = dup2(__ldg(&wuc[k * UDIM + n]));
            unsigned long long wr = dup2(__ldg(&wrc[k * UDIM + n]));
            FFMA2(au01, a01, wu);
            FFMA2(au23, a23, wu);
            FFMA2(ar01, a01, wr);
            FFMA2(ar23, a23, wr);
        }
        float pu[4], pr[4];
        unpack2(pu[0], pu[1], au01);
        unpack2(pu[2], pu[3], au23);
        unpack2(pr[0], pr[1], ar01);
        unpack2(pr[2], pr[3], ar23);

        float gu[4], h[4];
        #pragma unroll
        for (int r = 0; r < 4; r++) {
            gu[r]      = sigmoid_f(pu[r] + xu_[r] + bun);
            float grr  = sigmoid_f(pr[r] + xr_[r] + brn);
            h[r]       = grr * c_reg[r];
        }
        *(float4*)&h_s[n * 4] = make_float4(h[0], h[1], h[2], h[3]);
        __syncthreads();

        // ---- phase B: pre_c = (g_r*c) @ wcc[:,n] ----
        unsigned long long ac01 = 0ULL, ac23 = 0ULL;
        #pragma unroll 16
        for (int k = 0; k < UDIM; k++) {
            unsigned long long a01 = *(const unsigned long long*)&h_s[k * 4];
            unsigned long long a23 = *(const unsigned long long*)&h_s[k * 4 + 2];
            unsigned long long wc = dup2(__ldg(&wcc[k * UDIM + n]));
            FFMA2(ac01, a01, wc);
            FFMA2(ac23, a23, wc);
        }
        float pc[4];
        unpack2(pc[0], pc[1], ac01);
        unpack2(pc[2], pc[3], ac23);

        #pragma unroll
        for (int r = 0; r < 4; r++) {
            float cand = tanhf(pc[r] + xc_[r] + bcn);
            // c_new = gu*cand + (1-gu)*c
            c_reg[r] = fmaf(gu[r], cand - c_reg[r], c_reg[r]);
        }
        // All threads are past phase A (sync above), so c_s can be rewritten.
        *(float4*)&c_s[n * 4] = make_float4(c_reg[0], c_reg[1], c_reg[2], c_reg[3]);
        __syncthreads();
    }

    #pragma unroll
    for (int r = 0; r < 4; r++)
        out[(size_t)(r0 + r) * UDIM + n] = c_reg[r];
}

// =====================================================================
// Launch
// Inputs (metadata order):
//  0:x [256,512,256]  1:a0 [256,256]
//  2:wcx 3:wcc 4:bc   5:wux 6:wuc 7:bu   8:wrx 9:wrc 10:br
// =====================================================================
extern "C" void kernel_launch(void* const* d_in, const int* in_sizes, int n_in,
                              void* d_out, int out_size)
{
    const float* x   = (const float*)d_in[0];
    const float* a0  = (const float*)d_in[1];
    const float* wcx = (const float*)d_in[2];
    const float* wcc = (const float*)d_in[3];
    const float* bc  = (const float*)d_in[4];
    const float* wux = (const float*)d_in[5];
    const float* wuc = (const float*)d_in[6];
    const float* bu  = (const float*)d_in[7];
    const float* wrx = (const float*)d_in[8];
    const float* wrc = (const float*)d_in[9];
    const float* br  = (const float*)d_in[10];
    float* out = (float*)d_out;

    // Phase 1: x projections (z=0 -> wux, z=1 -> wrx, z=2 -> wcx)
    dim3 g1((MDIM * TDIM) / 128, UDIM / 128, 3);
    xproj_kernel<<<g1, 256>>>(x, wux, wrx, wcx);

    // Phase 2: sequential scan
    gru_scan_kernel<<<MDIM / 4, 256>>>(wuc, wrc, wcc, bu, br, bc, a0, out);
}